// round 5
// baseline (speedup 1.0000x reference)
#include <cuda_runtime.h>
#include <cstdint>

// Sort-based scatter-add, round 2 (R3 concept, R4-style ILP everywhere):
//  k_init   zero histogram + idx dtype detect
//  k_hist   dst histogram, 4 edges/thread (int4 loads, fire-and-forget REDs)
//  k_scan   single-block exclusive scan -> CSR offsets + cursor
//  k_bin    bin src by dst, 4 edges/thread (4 independent atomics in flight)
//  k_reduce 16 lanes/node, float4 chunk each; 4 gathers in flight per step;
//           register accumulation; ONE coalesced 256B store per node.
// Removes the ~410 MB of L2 atomic-RMW work that caps the direct-RED kernel.

#define MAX_E 800000
#define MAX_N 50000

__device__ int g_idx_is64;
__device__ int d_counts[MAX_N];
__device__ int d_cursor[MAX_N];
__device__ int d_offsets[MAX_N + 1];
__device__ int d_src_sorted[MAX_E];

__device__ __forceinline__ int load_idx(const void* ei_raw, int pos) {
    if (g_idx_is64) return (int)__ldg((const long long*)ei_raw + pos);
    return __ldg((const int*)ei_raw + pos);
}

__global__ void k_init(const int* __restrict__ ei_raw, int N) {
    int i = blockIdx.x * blockDim.x + threadIdx.x;
    if (i < N) d_counts[i] = 0;
    if (i == 0) {
        // values < 50000 => int64 layout has all-zero hi words
        int all_hi_zero = 1;
        for (int j = 0; j < 64; j++)
            if (ei_raw[2 * j + 1] != 0) { all_hi_zero = 0; break; }
        g_idx_is64 = all_hi_zero;
    }
}

// 4 edges per thread: one int4 load, 4 independent no-return atomics.
__global__ void k_hist(const void* __restrict__ ei_raw, int E, int G) {
    int g = blockIdx.x * blockDim.x + threadIdx.x;
    if (g >= G) return;
    int e0 = g << 2;
    int n = min(4, E - e0);

    int dst[4];
    if (!g_idx_is64 && n == 4) {
        int4 d4 = __ldg((const int4*)((const int*)ei_raw + e0));
        dst[0] = d4.x; dst[1] = d4.y; dst[2] = d4.z; dst[3] = d4.w;
    } else {
        #pragma unroll
        for (int k = 0; k < 4; k++)
            dst[k] = (k < n) ? load_idx(ei_raw, e0 + k) : 0;
    }
    #pragma unroll
    for (int k = 0; k < 4; k++)
        if (k < n) atomicAdd(&d_counts[dst[k]], 1);
}

// Single-block exclusive scan over N counts -> offsets (+ cursor init).
__global__ void k_scan(int N, int E) {
    __shared__ int s[1024];
    int t = threadIdx.x;
    int chunk = (N + 1023) / 1024;
    int lo = t * chunk;
    int hi = min(lo + chunk, N);

    int sum = 0;
    for (int i = lo; i < hi; i++) sum += d_counts[i];
    s[t] = sum;
    __syncthreads();
    for (int off = 1; off < 1024; off <<= 1) {
        int v = (t >= off) ? s[t - off] : 0;
        __syncthreads();
        s[t] += v;
        __syncthreads();
    }
    int run = (t > 0) ? s[t - 1] : 0;
    for (int i = lo; i < hi; i++) {
        d_offsets[i] = run;
        d_cursor[i] = run;
        run += d_counts[i];
    }
    if (t == 0) d_offsets[N] = E;
}

// 4 edges per thread: int4 index loads, 4 independent cursor atomics, 4 STGs.
__global__ void k_bin(const void* __restrict__ ei_raw, int E, int G) {
    int g = blockIdx.x * blockDim.x + threadIdx.x;
    if (g >= G) return;
    int e0 = g << 2;
    int n = min(4, E - e0);

    int dst[4], src[4];
    if (!g_idx_is64 && n == 4) {
        int4 d4 = __ldg((const int4*)((const int*)ei_raw + e0));
        int4 s4 = __ldg((const int4*)((const int*)ei_raw + E + e0));
        dst[0] = d4.x; dst[1] = d4.y; dst[2] = d4.z; dst[3] = d4.w;
        src[0] = s4.x; src[1] = s4.y; src[2] = s4.z; src[3] = s4.w;
    } else {
        #pragma unroll
        for (int k = 0; k < 4; k++) {
            int e = e0 + ((k < n) ? k : 0);
            dst[k] = load_idx(ei_raw, e);
            src[k] = load_idx(ei_raw, E + e);
        }
    }
    int pos[4];
    #pragma unroll
    for (int k = 0; k < 4; k++)          // 4 independent atomics in flight
        if (k < n) pos[k] = atomicAdd(&d_cursor[dst[k]], 1);
    #pragma unroll
    for (int k = 0; k < 4; k++)
        if (k < n) d_src_sorted[pos[k]] = src[k];
}

// 16 lanes/node, lane c owns float4 chunk c; 4 gathers in flight per step.
__global__ void k_reduce(const float* __restrict__ x,
                         float* __restrict__ out, int N) {
    int tid = blockIdx.x * blockDim.x + threadIdx.x;
    int node = tid >> 4;
    int c = tid & 15;
    if (node >= N) return;

    int beg = __ldg(&d_offsets[node]);
    int end = __ldg(&d_offsets[node + 1]);

    float4 acc = make_float4(0.f, 0.f, 0.f, 0.f);
    int i = beg;
    for (; i + 4 <= end; i += 4) {
        int s0 = __ldg(&d_src_sorted[i]);
        int s1 = __ldg(&d_src_sorted[i + 1]);
        int s2 = __ldg(&d_src_sorted[i + 2]);
        int s3 = __ldg(&d_src_sorted[i + 3]);
        float4 v0 = __ldg((const float4*)(x + (size_t)s0 * 64) + c);
        float4 v1 = __ldg((const float4*)(x + (size_t)s1 * 64) + c);
        float4 v2 = __ldg((const float4*)(x + (size_t)s2 * 64) + c);
        float4 v3 = __ldg((const float4*)(x + (size_t)s3 * 64) + c);
        acc.x += v0.x; acc.y += v0.y; acc.z += v0.z; acc.w += v0.w;
        acc.x += v1.x; acc.y += v1.y; acc.z += v1.z; acc.w += v1.w;
        acc.x += v2.x; acc.y += v2.y; acc.z += v2.z; acc.w += v2.w;
        acc.x += v3.x; acc.y += v3.y; acc.z += v3.z; acc.w += v3.w;
    }
    for (; i < end; i++) {
        int s = __ldg(&d_src_sorted[i]);
        float4 v = __ldg((const float4*)(x + (size_t)s * 64) + c);
        acc.x += v.x; acc.y += v.y; acc.z += v.z; acc.w += v.w;
    }
    ((float4*)(out + (size_t)node * 64))[c] = acc;
}

extern "C" void kernel_launch(void* const* d_in, const int* in_sizes, int n_in,
                              void* d_out, int out_size) {
    const float* x = (const float*)d_in[0];
    const void* ei = d_in[1];
    float* out = (float*)d_out;

    int E = in_sizes[1] / 2;          // edge_index is [2, E]
    int N = out_size / 64;
    int G = (E + 3) / 4;

    int tb = 256;
    k_init<<<(N + tb - 1) / tb, tb>>>((const int*)ei, N);
    k_hist<<<(G + tb - 1) / tb, tb>>>(ei, E, G);
    k_scan<<<1, 1024>>>(N, E);
    k_bin<<<(G + tb - 1) / tb, tb>>>(ei, E, G);
    long long total = (long long)N * 16;
    k_reduce<<<(int)((total + tb - 1) / tb), tb>>>(x, out, N);
}

// round 6
// speedup vs baseline: 2.7718x; 2.7718x over previous
#include <cuda_runtime.h>
#include <cstdint>

// Scatter-add message passing: out[dst] += x[src]
// x: [N, 64] fp32; edge_index: [2, E], int32 or int64 (detected on-device).
//
// Direct-RED design (sort-based rejected twice empirically):
//   k_zero_detect : zero out[] with float4 stores; thread (0,0) also detects
//                   index dtype (values < 50000 => int64 hi words all zero).
//   mp_scatter8   : 16 lanes per group of 8 consecutive edges; lane c owns
//                   float4 chunk c. Phases: 2x int4 index loads -> 8
//                   independent L2-only gathers -> 8 fire-and-forget v4 REDs.
//                   8-deep MLP targets L1/LSU saturation (R4: L1=71%, MLP=4).

__device__ int g_idx_is64;

__global__ void k_zero_detect(float4* __restrict__ out, int n4,
                              const int* __restrict__ ei_raw) {
    int i = blockIdx.x * blockDim.x + threadIdx.x;
    if (i < n4) out[i] = make_float4(0.f, 0.f, 0.f, 0.f);
    if (i == 0) {
        int all_hi_zero = 1;
        #pragma unroll
        for (int j = 0; j < 64; j++)
            if (ei_raw[2 * j + 1] != 0) { all_hi_zero = 0; break; }
        g_idx_is64 = all_hi_zero;
    }
}

__device__ __forceinline__ void red_v4(float* out, int dst, int c, float4 v) {
    float4* op = (float4*)(out + (size_t)dst * 64) + c;
    asm volatile("red.global.add.v4.f32 [%0], {%1, %2, %3, %4};"
                 :: "l"(op), "f"(v.x), "f"(v.y), "f"(v.z), "f"(v.w)
                 : "memory");
}

// L2-only float4 load (bypass L1: x has ~2% L1 hit rate at 12.8 MB working set)
__device__ __forceinline__ float4 ldcg_f4(const float4* p) {
    float4 v;
    asm volatile("ld.global.cg.v4.f32 {%0, %1, %2, %3}, [%4];"
                 : "=f"(v.x), "=f"(v.y), "=f"(v.z), "=f"(v.w) : "l"(p));
    return v;
}

__global__ void mp_scatter8_kernel(const float* __restrict__ x,
                                   const void* __restrict__ ei_raw,
                                   float* __restrict__ out,
                                   int E, int G) {
    int tid = blockIdx.x * blockDim.x + threadIdx.x;
    int g = tid >> 4;           // group of 8 consecutive edges
    int c = tid & 15;           // float4 chunk within the 64-float row
    if (g >= G) return;

    int e0 = g << 3;
    int n = min(8, E - e0);     // edges in this group (tail-safe)

    int dst[8], src[8];
    if (g_idx_is64) {
        const long long* ei = (const long long*)ei_raw;
        #pragma unroll
        for (int k = 0; k < 8; k++) {
            int e = e0 + ((k < n) ? k : 0);
            dst[k] = (int)__ldg(ei + e);
            src[k] = (int)__ldg(ei + E + e);
        }
    } else {
        const int* ei = (const int*)ei_raw;
        if (n == 8) {           // aligned: e0 % 8 == 0
            int4 d0 = __ldg((const int4*)(ei + e0));
            int4 d1 = __ldg((const int4*)(ei + e0 + 4));
            int4 s0 = __ldg((const int4*)(ei + E + e0));
            int4 s1 = __ldg((const int4*)(ei + E + e0 + 4));
            dst[0] = d0.x; dst[1] = d0.y; dst[2] = d0.z; dst[3] = d0.w;
            dst[4] = d1.x; dst[5] = d1.y; dst[6] = d1.z; dst[7] = d1.w;
            src[0] = s0.x; src[1] = s0.y; src[2] = s0.z; src[3] = s0.w;
            src[4] = s1.x; src[5] = s1.y; src[6] = s1.z; src[7] = s1.w;
        } else {
            #pragma unroll
            for (int k = 0; k < 8; k++) {
                int e = e0 + ((k < n) ? k : 0);
                dst[k] = __ldg(ei + e);
                src[k] = __ldg(ei + E + e);
            }
        }
    }

    // Phase 2: all 8 gathers in flight before any RED (asm memory clobber
    // would otherwise serialize load->red pairs).
    float4 v[8];
    #pragma unroll
    for (int k = 0; k < 8; k++)
        v[k] = ldcg_f4((const float4*)(x + (size_t)src[k] * 64) + c);

    // Phase 3: fire-and-forget reductions.
    #pragma unroll
    for (int k = 0; k < 8; k++)
        if (k < n) red_v4(out, dst[k], c, v[k]);
}

extern "C" void kernel_launch(void* const* d_in, const int* in_sizes, int n_in,
                              void* d_out, int out_size) {
    const float* x = (const float*)d_in[0];
    const void* ei = d_in[1];
    float* out = (float*)d_out;

    int E = in_sizes[1] / 2;            // edge_index is [2, E]
    int G = (E + 7) / 8;                // groups of 8 edges

    int n4 = out_size / 4;              // float4 count of out
    int tb = 256;
    k_zero_detect<<<(n4 + tb - 1) / tb, tb>>>((float4*)out, n4,
                                              (const int*)ei);

    long long total = (long long)G * 16;
    int blocks = (int)((total + tb - 1) / tb);
    mp_scatter8_kernel<<<blocks, tb>>>(x, ei, out, E, G);
}

// round 8
// speedup vs baseline: 2.7935x; 1.0078x over previous
#include <cuda_runtime.h>
#include <cstdint>

// Scatter-add message passing: out[dst] += x[src]
// x: [N, 64] fp32; edge_index: [2, E], int32 or int64 (detected on-device).
//
// Lock-in of measured-best pieces (R8 = R7 retry; R7 hit an infra failure):
//  - R4 kernel: 16 lanes per group of 4 edges, lane c owns float4 chunk c.
//    Phases: int4 index loads -> 4 independent gathers -> 4 v4 REDs.
//    MLP=4 keeps regs at ~28 -> full occupancy (R6's MLP=8 cost 33% occ and
//    regressed the kernel 42.3 -> 44.5 us).
//  - R6 wrapper: fused zero+detect kernel (2 launches total).

__device__ int g_idx_is64;

__global__ void k_zero_detect(float4* __restrict__ out, int n4,
                              const int* __restrict__ ei_raw) {
    int i = blockIdx.x * blockDim.x + threadIdx.x;
    if (i < n4) out[i] = make_float4(0.f, 0.f, 0.f, 0.f);
    if (i == 0) {
        // values < 50000 => int64 layout has all-zero hi words
        int all_hi_zero = 1;
        #pragma unroll
        for (int j = 0; j < 64; j++)
            if (ei_raw[2 * j + 1] != 0) { all_hi_zero = 0; break; }
        g_idx_is64 = all_hi_zero;
    }
}

__device__ __forceinline__ void red_v4(float* out, int dst, int c, float4 v) {
    float4* op = (float4*)(out + (size_t)dst * 64) + c;
    asm volatile("red.global.add.v4.f32 [%0], {%1, %2, %3, %4};"
                 :: "l"(op), "f"(v.x), "f"(v.y), "f"(v.z), "f"(v.w)
                 : "memory");
}

__global__ void __launch_bounds__(256, 8)
mp_scatter4_kernel(const float* __restrict__ x,
                   const void* __restrict__ ei_raw,
                   float* __restrict__ out,
                   int E, int G) {
    int tid = blockIdx.x * blockDim.x + threadIdx.x;
    int g = tid >> 4;           // group of 4 consecutive edges
    int c = tid & 15;           // float4 chunk within the 64-float row
    if (g >= G) return;

    int e0 = g << 2;
    int n = min(4, E - e0);     // edges in this group (tail-safe)

    int dst[4], src[4];
    if (g_idx_is64) {
        const long long* ei = (const long long*)ei_raw;
        #pragma unroll
        for (int k = 0; k < 4; k++) {
            int e = e0 + ((k < n) ? k : 0);
            dst[k] = (int)__ldg(ei + e);
            src[k] = (int)__ldg(ei + E + e);
        }
    } else {
        const int* ei = (const int*)ei_raw;
        if (n == 4) {           // aligned: e0 % 4 == 0
            int4 d4 = __ldg((const int4*)(ei + e0));
            int4 s4 = __ldg((const int4*)(ei + E + e0));
            dst[0] = d4.x; dst[1] = d4.y; dst[2] = d4.z; dst[3] = d4.w;
            src[0] = s4.x; src[1] = s4.y; src[2] = s4.z; src[3] = s4.w;
        } else {
            #pragma unroll
            for (int k = 0; k < 4; k++) {
                int e = e0 + ((k < n) ? k : 0);
                dst[k] = __ldg(ei + e);
                src[k] = __ldg(ei + E + e);
            }
        }
    }

    // Phase 2: all 4 gathers in flight before any RED (asm memory clobber
    // would otherwise serialize load->red pairs).
    float4 v[4];
    #pragma unroll
    for (int k = 0; k < 4; k++)
        v[k] = __ldg((const float4*)(x + (size_t)src[k] * 64) + c);

    // Phase 3: fire-and-forget reductions.
    #pragma unroll
    for (int k = 0; k < 4; k++)
        if (k < n) red_v4(out, dst[k], c, v[k]);
}

extern "C" void kernel_launch(void* const* d_in, const int* in_sizes, int n_in,
                              void* d_out, int out_size) {
    const float* x = (const float*)d_in[0];
    const void* ei = d_in[1];
    float* out = (float*)d_out;

    int E = in_sizes[1] / 2;            // edge_index is [2, E]
    int G = (E + 3) / 4;                // groups of 4 edges

    int n4 = out_size / 4;              // float4 count of out
    int tb = 256;
    k_zero_detect<<<(n4 + tb - 1) / tb, tb>>>((float4*)out, n4,
                                              (const int*)ei);

    long long total = (long long)G * 16;
    int blocks = (int)((total + tb - 1) / tb);
    mp_scatter4_kernel<<<blocks, tb>>>(x, ei, out, E, G);
}